// round 1
// baseline (speedup 1.0000x reference)
#include <cuda_runtime.h>
#include <cstdint>

// GINConv: out = (1+eps)*feat + segment_sum(feat[edge_src] -> edge_dst)
// N=100000 nodes, D=64 fp32 features, E=1200000 edges.
// Inputs (metadata order): feat [N*D] f32, eps [1] f32, edge_src [E] i32, edge_dst [E] i32.
// Output: [N*D] f32.
//
// Strategy: everything fits in L2 (~61MB total). Two kernels:
//   1) init: out = (1+eps)*feat  (float4 vectorized)
//   2) edges: 16 threads/edge, each handles one float4 of the 64-float row,
//      gather from feat (L2-resident) and red.global.add.v4.f32 into out.

static constexpr int D4 = 16;  // 64 floats = 16 float4

__global__ void gin_init_kernel(const float4* __restrict__ feat,
                                const float* __restrict__ eps,
                                float4* __restrict__ out,
                                int n4) {
    int i = blockIdx.x * blockDim.x + threadIdx.x;
    if (i >= n4) return;
    float s = 1.0f + __ldg(eps);
    float4 f = __ldg(feat + i);
    f.x *= s; f.y *= s; f.z *= s; f.w *= s;
    out[i] = f;
}

__global__ void __launch_bounds__(256) gin_edge_kernel(
    const float4* __restrict__ feat,
    const int* __restrict__ edge_src,
    const int* __restrict__ edge_dst,
    float4* __restrict__ out,
    int n_edges) {
    int gid = blockIdx.x * blockDim.x + threadIdx.x;
    int eid = gid >> 4;         // 16 threads per edge
    int lane = gid & 15;        // which float4 of the row
    if (eid >= n_edges) return;

    int s = __ldg(edge_src + eid);
    int d = __ldg(edge_dst + eid);

    float4 v = __ldg(feat + (long long)s * D4 + lane);
    float4* dst = out + (long long)d * D4 + lane;

    // Vector fp32 reduction (no return value) — 1 instruction for 16 bytes.
    asm volatile(
        "red.global.add.v4.f32 [%0], {%1, %2, %3, %4};"
        :: "l"(dst), "f"(v.x), "f"(v.y), "f"(v.z), "f"(v.w)
        : "memory");
}

extern "C" void kernel_launch(void* const* d_in, const int* in_sizes, int n_in,
                              void* d_out, int out_size) {
    const float* feat     = (const float*)d_in[0];
    const float* eps      = (const float*)d_in[1];
    const int*   edge_src = (const int*)d_in[2];
    const int*   edge_dst = (const int*)d_in[3];
    float*       out      = (float*)d_out;

    int n_feat  = in_sizes[0];      // N * 64
    int n_edges = in_sizes[2];      // E

    // Kernel 1: out = (1+eps)*feat
    int n4 = n_feat / 4;
    {
        int threads = 256;
        int blocks = (n4 + threads - 1) / threads;
        gin_init_kernel<<<blocks, threads>>>(
            (const float4*)feat, eps, (float4*)out, n4);
    }

    // Kernel 2: scatter-add edges (stream-ordered after init)
    {
        long long total_threads = (long long)n_edges * 16;
        int threads = 256;
        long long blocks = (total_threads + threads - 1) / threads;
        gin_edge_kernel<<<(int)blocks, threads>>>(
            (const float4*)feat, edge_src, edge_dst, (float4*)out, n_edges);
    }
}

// round 2
// speedup vs baseline: 1.1299x; 1.1299x over previous
#include <cuda_runtime.h>
#include <cstdint>

// GINConv: out = (1+eps)*feat + segment_sum(feat[edge_src] -> edge_dst)
// N=100000 nodes, D=64 fp32, E=1200000 edges.
//
// Round-2 strategy: the atomic scatter-add was ~half the L2 traffic plus LTS
// atomic-ALU load. Build a dst-bucketed edge list (CSR) on-device each call
// (deterministic pipeline: zero -> histogram -> 3-stage scan -> scatter),
// then one pure-gather kernel: 16 threads/node accumulate in registers and
// write each output float4 exactly once. ~363MB L2 traffic vs ~620MB before.

static constexpr int D4 = 16;              // 64 floats = 16 float4 per row
static constexpr int SCAN_BLOCKS = 256;    // covers 256*512 = 131072 nodes
static constexpr int CHUNK = 512;          // nodes per scan block
static constexpr int N_MAX = SCAN_BLOCKS * CHUNK;
static constexpr int E_MAX = 1200000;

__device__ int g_deg[N_MAX];
__device__ int g_off[N_MAX + 1];
__device__ int g_cur[N_MAX];
__device__ int g_src_sorted[E_MAX];
__device__ int g_part[SCAN_BLOCKS];

// ---------- build pipeline ----------

__global__ void zero_deg_kernel(int n_nodes) {
    int i = blockIdx.x * blockDim.x + threadIdx.x;
    if (i < n_nodes) g_deg[i] = 0;
}

__global__ void hist_kernel(const int* __restrict__ edge_dst, int n_edges) {
    int i = blockIdx.x * blockDim.x + threadIdx.x;
    if (i < n_edges) atomicAdd(&g_deg[edge_dst[i]], 1);
}

// block-wide exclusive scan for 256 threads; returns exclusive prefix of v
__device__ __forceinline__ int block_exscan_256(int v) {
    int lane = threadIdx.x & 31;
    int warp = threadIdx.x >> 5;
    int x = v;
#pragma unroll
    for (int o = 1; o < 32; o <<= 1) {
        int y = __shfl_up_sync(0xFFFFFFFFu, x, o);
        if (lane >= o) x += y;
    }
    __shared__ int wsum[8];
    if (lane == 31) wsum[warp] = x;
    __syncthreads();
    if (warp == 0) {
        int w = (lane < 8) ? wsum[lane] : 0;
#pragma unroll
        for (int o = 1; o < 8; o <<= 1) {
            int y = __shfl_up_sync(0xFFFFFFFFu, w, o);
            if (lane >= o) w += y;
        }
        if (lane < 8) wsum[lane] = w;  // inclusive warp sums
    }
    __syncthreads();
    int base = (warp > 0) ? wsum[warp - 1] : 0;
    return base + x - v;  // exclusive
}

// stage 1: per-block degree totals
__global__ void scan_reduce_kernel(int n_nodes) {
    int b = blockIdx.x;
    int i0 = b * CHUNK + threadIdx.x * 2;
    int v0 = (i0     < n_nodes) ? g_deg[i0]     : 0;
    int v1 = (i0 + 1 < n_nodes) ? g_deg[i0 + 1] : 0;
    int v = v0 + v1;
    int ex = block_exscan_256(v);
    if (threadIdx.x == 255) g_part[b] = ex + v;  // block total
}

// stage 2: exclusive scan of 256 block totals (one block)
__global__ void scan_partials_kernel() {
    int t = threadIdx.x;
    int v = g_part[t];
    int ex = block_exscan_256(v);
    g_part[t] = ex;
}

// stage 3: per-block exclusive scan + block base -> offsets & cursors
__global__ void scan_write_kernel(int n_nodes, int n_edges) {
    int b = blockIdx.x;
    int i0 = b * CHUNK + threadIdx.x * 2;
    int v0 = (i0     < n_nodes) ? g_deg[i0]     : 0;
    int v1 = (i0 + 1 < n_nodes) ? g_deg[i0 + 1] : 0;
    int ex = block_exscan_256(v0 + v1) + g_part[b];
    if (i0 < n_nodes)     { g_off[i0] = ex;          g_cur[i0] = ex; }
    if (i0 + 1 < n_nodes) { g_off[i0 + 1] = ex + v0; g_cur[i0 + 1] = ex + v0; }
    if (b == 0 && threadIdx.x == 0) g_off[n_nodes] = n_edges;
}

__global__ void scatter_kernel(const int* __restrict__ edge_src,
                               const int* __restrict__ edge_dst,
                               int n_edges) {
    int i = blockIdx.x * blockDim.x + threadIdx.x;
    if (i >= n_edges) return;
    int d = edge_dst[i];
    int pos = atomicAdd(&g_cur[d], 1);
    g_src_sorted[pos] = edge_src[i];
}

// ---------- main gather (16 threads per node, float4 per lane) ----------

__global__ void __launch_bounds__(256) gin_gather_kernel(
    const float4* __restrict__ feat,
    const float* __restrict__ eps,
    float4* __restrict__ out,
    int n_nodes) {
    int gid = blockIdx.x * blockDim.x + threadIdx.x;
    int node = gid >> 4;
    int lane = gid & 15;
    if (node >= n_nodes) return;

    int beg = g_off[node];
    int end = g_off[node + 1];

    float4 acc = make_float4(0.f, 0.f, 0.f, 0.f);

    int e = beg;
    // unroll x4: keep 4 independent feat loads in flight per thread
    for (; e + 4 <= end; e += 4) {
        int s0 = g_src_sorted[e];
        int s1 = g_src_sorted[e + 1];
        int s2 = g_src_sorted[e + 2];
        int s3 = g_src_sorted[e + 3];
        float4 v0 = __ldg(feat + (size_t)s0 * D4 + lane);
        float4 v1 = __ldg(feat + (size_t)s1 * D4 + lane);
        float4 v2 = __ldg(feat + (size_t)s2 * D4 + lane);
        float4 v3 = __ldg(feat + (size_t)s3 * D4 + lane);
        acc.x += v0.x + v1.x + v2.x + v3.x;
        acc.y += v0.y + v1.y + v2.y + v3.y;
        acc.z += v0.z + v1.z + v2.z + v3.z;
        acc.w += v0.w + v1.w + v2.w + v3.w;
    }
    for (; e < end; ++e) {
        int s = g_src_sorted[e];
        float4 v = __ldg(feat + (size_t)s * D4 + lane);
        acc.x += v.x; acc.y += v.y; acc.z += v.z; acc.w += v.w;
    }

    float sc = 1.0f + __ldg(eps);
    float4 f = __ldg(feat + (size_t)node * D4 + lane);
    float4 o;
    o.x = fmaf(sc, f.x, acc.x);
    o.y = fmaf(sc, f.y, acc.y);
    o.z = fmaf(sc, f.z, acc.z);
    o.w = fmaf(sc, f.w, acc.w);
    out[(size_t)node * D4 + lane] = o;
}

// ---------- fallback (atomic) path, in case shapes exceed static scratch ----------

__global__ void gin_init_kernel(const float4* __restrict__ feat,
                                const float* __restrict__ eps,
                                float4* __restrict__ out,
                                int n4) {
    int i = blockIdx.x * blockDim.x + threadIdx.x;
    if (i >= n4) return;
    float s = 1.0f + __ldg(eps);
    float4 f = __ldg(feat + i);
    f.x *= s; f.y *= s; f.z *= s; f.w *= s;
    out[i] = f;
}

__global__ void __launch_bounds__(256) gin_edge_atomic_kernel(
    const float4* __restrict__ feat,
    const int* __restrict__ edge_src,
    const int* __restrict__ edge_dst,
    float4* __restrict__ out,
    int n_edges) {
    int gid = blockIdx.x * blockDim.x + threadIdx.x;
    int eid = gid >> 4;
    int lane = gid & 15;
    if (eid >= n_edges) return;
    int s = __ldg(edge_src + eid);
    int d = __ldg(edge_dst + eid);
    float4 v = __ldg(feat + (size_t)s * D4 + lane);
    float4* dst = out + (size_t)d * D4 + lane;
    asm volatile(
        "red.global.add.v4.f32 [%0], {%1, %2, %3, %4};"
        :: "l"(dst), "f"(v.x), "f"(v.y), "f"(v.z), "f"(v.w)
        : "memory");
}

extern "C" void kernel_launch(void* const* d_in, const int* in_sizes, int n_in,
                              void* d_out, int out_size) {
    const float* feat     = (const float*)d_in[0];
    const float* eps      = (const float*)d_in[1];
    const int*   edge_src = (const int*)d_in[2];
    const int*   edge_dst = (const int*)d_in[3];
    float*       out      = (float*)d_out;

    int n_feat  = in_sizes[0];          // N * 64
    int n_edges = in_sizes[2];          // E
    int n_nodes = n_feat / 64;

    if (n_nodes > N_MAX || n_edges > E_MAX) {
        // Fallback: atomic path (no static scratch limits)
        int n4 = n_feat / 4;
        gin_init_kernel<<<(n4 + 255) / 256, 256>>>(
            (const float4*)feat, eps, (float4*)out, n4);
        long long total = (long long)n_edges * 16;
        gin_edge_atomic_kernel<<<(int)((total + 255) / 256), 256>>>(
            (const float4*)feat, edge_src, edge_dst, (float4*)out, n_edges);
        return;
    }

    // 1. zero degrees
    zero_deg_kernel<<<(n_nodes + 255) / 256, 256>>>(n_nodes);
    // 2. histogram destinations
    hist_kernel<<<(n_edges + 255) / 256, 256>>>(edge_dst, n_edges);
    // 3-5. exclusive scan (reduce, scan partials, write offsets+cursors)
    scan_reduce_kernel<<<SCAN_BLOCKS, 256>>>(n_nodes);
    scan_partials_kernel<<<1, 256>>>();
    scan_write_kernel<<<SCAN_BLOCKS, 256>>>(n_nodes, n_edges);
    // 6. scatter edge sources into dst-buckets
    scatter_kernel<<<(n_edges + 255) / 256, 256>>>(edge_src, edge_dst, n_edges);
    // 7. gather + residual, one write per output element
    {
        long long total = (long long)n_nodes * 16;
        gin_gather_kernel<<<(int)((total + 255) / 256), 256>>>(
            (const float4*)feat, eps, (float4*)out, n_nodes);
    }
}

// round 3
// speedup vs baseline: 1.1311x; 1.0011x over previous
#include <cuda_runtime.h>
#include <cstdint>

// GINConv: out = (1+eps)*feat + segment_sum(feat[edge_src] -> edge_dst)
// N=100000 nodes, D=64 fp32, E=1200000 edges.
//
// Round-3: the CSR build's tiny dependent kernels dominated overhead
// (scan_partials alone = 3.9us). Cut 7 launches -> 5:
//  - g_deg zeroing is an invariant: zero at module load, re-zeroed by
//    scan_write each call after it consumes the degrees.
//  - scan_partials removed: every scan_write block redundantly scans the
//    256 block partials itself (256 ints, trivial).
//  - hist/scatter use int4 loads (4 edges/thread) for MLP.

static constexpr int D4 = 16;              // 64 floats = 16 float4 per row
static constexpr int SCAN_BLOCKS = 256;    // covers 256*512 = 131072 nodes
static constexpr int CHUNK = 512;          // nodes per scan block
static constexpr int N_MAX = SCAN_BLOCKS * CHUNK;
static constexpr int E_MAX = 1200000;

__device__ int g_deg[N_MAX];               // zero-init at load; invariant: zero on entry
__device__ int g_off[N_MAX + 1];
__device__ int g_cur[N_MAX];
__device__ int g_src_sorted[E_MAX];
__device__ int g_part[SCAN_BLOCKS];

// ---------- build pipeline ----------

__global__ void hist_kernel(const int* __restrict__ edge_dst, int n_edges) {
    int i4 = blockIdx.x * blockDim.x + threadIdx.x;
    int base = i4 * 4;
    if (base + 3 < n_edges) {
        int4 d = __ldg((const int4*)(edge_dst + base));
        atomicAdd(&g_deg[d.x], 1);
        atomicAdd(&g_deg[d.y], 1);
        atomicAdd(&g_deg[d.z], 1);
        atomicAdd(&g_deg[d.w], 1);
    } else {
        for (int i = base; i < n_edges; ++i)
            atomicAdd(&g_deg[__ldg(edge_dst + i)], 1);
    }
}

// block-wide exclusive scan for 256 threads; returns exclusive prefix of v
__device__ __forceinline__ int block_exscan_256(int v) {
    int lane = threadIdx.x & 31;
    int warp = threadIdx.x >> 5;
    int x = v;
#pragma unroll
    for (int o = 1; o < 32; o <<= 1) {
        int y = __shfl_up_sync(0xFFFFFFFFu, x, o);
        if (lane >= o) x += y;
    }
    __shared__ int wsum[8];
    if (lane == 31) wsum[warp] = x;
    __syncthreads();
    if (warp == 0) {
        int w = (lane < 8) ? wsum[lane] : 0;
#pragma unroll
        for (int o = 1; o < 8; o <<= 1) {
            int y = __shfl_up_sync(0xFFFFFFFFu, w, o);
            if (lane >= o) w += y;
        }
        if (lane < 8) wsum[lane] = w;  // inclusive warp sums
    }
    __syncthreads();
    int base = (warp > 0) ? wsum[warp - 1] : 0;
    return base + x - v;  // exclusive
}

// stage 1: per-block degree totals
__global__ void scan_reduce_kernel(int n_nodes) {
    int b = blockIdx.x;
    int i0 = b * CHUNK + threadIdx.x * 2;
    int v0 = (i0     < n_nodes) ? g_deg[i0]     : 0;
    int v1 = (i0 + 1 < n_nodes) ? g_deg[i0 + 1] : 0;
    int v = v0 + v1;
    int ex = block_exscan_256(v);
    if (threadIdx.x == 255) g_part[b] = ex + v;  // block total
}

// stage 2: per-block scan + in-block partials scan -> offsets & cursors.
// Also re-zeros g_deg for the next call (invariant).
__global__ void scan_write_kernel(int n_nodes, int n_edges) {
    int b = blockIdx.x;

    // Redundantly scan all 256 partials in this block to get our base.
    __shared__ int s_base;
    {
        int t = threadIdx.x;
        int v = g_part[t];
        int ex = block_exscan_256(v);
        __shared__ int s_ex[SCAN_BLOCKS];
        s_ex[t] = ex;
        __syncthreads();
        if (t == 0) s_base = s_ex[b];
        __syncthreads();
    }

    int i0 = b * CHUNK + threadIdx.x * 2;
    int v0 = (i0     < n_nodes) ? g_deg[i0]     : 0;
    int v1 = (i0 + 1 < n_nodes) ? g_deg[i0 + 1] : 0;
    int ex = block_exscan_256(v0 + v1) + s_base;
    if (i0 < n_nodes)     { g_off[i0]     = ex;      g_cur[i0]     = ex;      g_deg[i0]     = 0; }
    if (i0 + 1 < n_nodes) { g_off[i0 + 1] = ex + v0; g_cur[i0 + 1] = ex + v0; g_deg[i0 + 1] = 0; }
    if (b == 0 && threadIdx.x == 0) g_off[n_nodes] = n_edges;
}

__global__ void scatter_kernel(const int* __restrict__ edge_src,
                               const int* __restrict__ edge_dst,
                               int n_edges) {
    int i4 = blockIdx.x * blockDim.x + threadIdx.x;
    int base = i4 * 4;
    if (base + 3 < n_edges) {
        int4 d = __ldg((const int4*)(edge_dst + base));
        int4 s = __ldg((const int4*)(edge_src + base));
        int p0 = atomicAdd(&g_cur[d.x], 1);
        int p1 = atomicAdd(&g_cur[d.y], 1);
        int p2 = atomicAdd(&g_cur[d.z], 1);
        int p3 = atomicAdd(&g_cur[d.w], 1);
        g_src_sorted[p0] = s.x;
        g_src_sorted[p1] = s.y;
        g_src_sorted[p2] = s.z;
        g_src_sorted[p3] = s.w;
    } else {
        for (int i = base; i < n_edges; ++i) {
            int d = __ldg(edge_dst + i);
            int pos = atomicAdd(&g_cur[d], 1);
            g_src_sorted[pos] = __ldg(edge_src + i);
        }
    }
}

// ---------- main gather (16 threads per node, float4 per lane) ----------

__global__ void __launch_bounds__(256) gin_gather_kernel(
    const float4* __restrict__ feat,
    const float* __restrict__ eps,
    float4* __restrict__ out,
    int n_nodes) {
    int gid = blockIdx.x * blockDim.x + threadIdx.x;
    int node = gid >> 4;
    int lane = gid & 15;
    if (node >= n_nodes) return;

    int beg = g_off[node];
    int end = g_off[node + 1];

    float4 acc = make_float4(0.f, 0.f, 0.f, 0.f);

    int e = beg;
    for (; e + 4 <= end; e += 4) {
        int s0 = g_src_sorted[e];
        int s1 = g_src_sorted[e + 1];
        int s2 = g_src_sorted[e + 2];
        int s3 = g_src_sorted[e + 3];
        float4 v0 = __ldg(feat + (size_t)s0 * D4 + lane);
        float4 v1 = __ldg(feat + (size_t)s1 * D4 + lane);
        float4 v2 = __ldg(feat + (size_t)s2 * D4 + lane);
        float4 v3 = __ldg(feat + (size_t)s3 * D4 + lane);
        acc.x += v0.x + v1.x + v2.x + v3.x;
        acc.y += v0.y + v1.y + v2.y + v3.y;
        acc.z += v0.z + v1.z + v2.z + v3.z;
        acc.w += v0.w + v1.w + v2.w + v3.w;
    }
    for (; e < end; ++e) {
        int s = g_src_sorted[e];
        float4 v = __ldg(feat + (size_t)s * D4 + lane);
        acc.x += v.x; acc.y += v.y; acc.z += v.z; acc.w += v.w;
    }

    float sc = 1.0f + __ldg(eps);
    float4 f = __ldg(feat + (size_t)node * D4 + lane);
    float4 o;
    o.x = fmaf(sc, f.x, acc.x);
    o.y = fmaf(sc, f.y, acc.y);
    o.z = fmaf(sc, f.z, acc.z);
    o.w = fmaf(sc, f.w, acc.w);
    out[(size_t)node * D4 + lane] = o;
}

// ---------- fallback (atomic) path for unexpected shapes ----------

__global__ void gin_init_kernel(const float4* __restrict__ feat,
                                const float* __restrict__ eps,
                                float4* __restrict__ out,
                                int n4) {
    int i = blockIdx.x * blockDim.x + threadIdx.x;
    if (i >= n4) return;
    float s = 1.0f + __ldg(eps);
    float4 f = __ldg(feat + i);
    f.x *= s; f.y *= s; f.z *= s; f.w *= s;
    out[i] = f;
}

__global__ void __launch_bounds__(256) gin_edge_atomic_kernel(
    const float4* __restrict__ feat,
    const int* __restrict__ edge_src,
    const int* __restrict__ edge_dst,
    float4* __restrict__ out,
    int n_edges) {
    int gid = blockIdx.x * blockDim.x + threadIdx.x;
    int eid = gid >> 4;
    int lane = gid & 15;
    if (eid >= n_edges) return;
    int s = __ldg(edge_src + eid);
    int d = __ldg(edge_dst + eid);
    float4 v = __ldg(feat + (size_t)s * D4 + lane);
    float4* dst = out + (size_t)d * D4 + lane;
    asm volatile(
        "red.global.add.v4.f32 [%0], {%1, %2, %3, %4};"
        :: "l"(dst), "f"(v.x), "f"(v.y), "f"(v.z), "f"(v.w)
        : "memory");
}

extern "C" void kernel_launch(void* const* d_in, const int* in_sizes, int n_in,
                              void* d_out, int out_size) {
    const float* feat     = (const float*)d_in[0];
    const float* eps      = (const float*)d_in[1];
    const int*   edge_src = (const int*)d_in[2];
    const int*   edge_dst = (const int*)d_in[3];
    float*       out      = (float*)d_out;

    int n_feat  = in_sizes[0];          // N * 64
    int n_edges = in_sizes[2];          // E
    int n_nodes = n_feat / 64;

    if (n_nodes > N_MAX || n_edges > E_MAX) {
        int n4 = n_feat / 4;
        gin_init_kernel<<<(n4 + 255) / 256, 256>>>(
            (const float4*)feat, eps, (float4*)out, n4);
        long long total = (long long)n_edges * 16;
        gin_edge_atomic_kernel<<<(int)((total + 255) / 256), 256>>>(
            (const float4*)feat, edge_src, edge_dst, (float4*)out, n_edges);
        return;
    }

    int e4 = (n_edges + 3) / 4;

    // 1. histogram destinations (g_deg is zero by invariant)
    hist_kernel<<<(e4 + 255) / 256, 256>>>(edge_dst, n_edges);
    // 2-3. exclusive scan (reduce; write offsets+cursors, re-zero g_deg)
    scan_reduce_kernel<<<SCAN_BLOCKS, 256>>>(n_nodes);
    scan_write_kernel<<<SCAN_BLOCKS, 256>>>(n_nodes, n_edges);
    // 4. scatter edge sources into dst-buckets
    scatter_kernel<<<(e4 + 255) / 256, 256>>>(edge_src, edge_dst, n_edges);
    // 5. gather + residual, one write per output element
    {
        long long total = (long long)n_nodes * 16;
        gin_gather_kernel<<<(int)((total + 255) / 256), 256>>>(
            (const float4*)feat, eps, (float4*)out, n_nodes);
    }
}

// round 4
// speedup vs baseline: 1.3797x; 1.2198x over previous
#include <cuda_runtime.h>
#include <cstdint>

// GINConv: out = (1+eps)*feat + segment_sum(feat[edge_src] -> edge_dst)
// N=100000 nodes, D=64 fp32, E=1200000 edges.
//
// Round-4: exact CSR (hist+scan) replaced by fixed-capacity buckets.
// Degrees ~ Poisson(12); CAP=64 gives P(overflow) ~ 1e-25 per node, and any
// overflow is still handled correctly via an overflow list + atomic tail
// kernel. Pipeline: scatter_bucket -> gather -> overflow_tail (3 launches).
// Invariants maintained across graph replays: g_cnt zeroed by gather,
// g_ovf_cnt zeroed by tail.

static constexpr int D4 = 16;          // 64 floats = 16 float4 per row
static constexpr int CAP = 64;         // bucket capacity per node
static constexpr int N_MAX = 131072;
static constexpr int E_MAX = 1200000;
static constexpr int OVF_MAX = 65536;

__device__ int g_cnt[N_MAX];               // zero-init at load; zero on entry (invariant)
__device__ int g_bucket[(size_t)N_MAX * CAP];
__device__ int g_ovf_cnt;                  // zero on entry (invariant)
__device__ int2 g_ovf[OVF_MAX];            // (dst, src) overflow edges

// ---------- scatter into buckets ----------

__global__ void __launch_bounds__(256) scatter_bucket_kernel(
    const int* __restrict__ edge_src,
    const int* __restrict__ edge_dst,
    int n_edges) {
    int i4 = blockIdx.x * blockDim.x + threadIdx.x;
    int base = i4 * 4;
    if (base + 3 < n_edges) {
        int4 d = __ldg((const int4*)(edge_dst + base));
        int4 s = __ldg((const int4*)(edge_src + base));
        int p0 = atomicAdd(&g_cnt[d.x], 1);
        int p1 = atomicAdd(&g_cnt[d.y], 1);
        int p2 = atomicAdd(&g_cnt[d.z], 1);
        int p3 = atomicAdd(&g_cnt[d.w], 1);
        if (p0 < CAP) g_bucket[(size_t)d.x * CAP + p0] = s.x;
        else { int o = atomicAdd(&g_ovf_cnt, 1); if (o < OVF_MAX) g_ovf[o] = make_int2(d.x, s.x); }
        if (p1 < CAP) g_bucket[(size_t)d.y * CAP + p1] = s.y;
        else { int o = atomicAdd(&g_ovf_cnt, 1); if (o < OVF_MAX) g_ovf[o] = make_int2(d.y, s.y); }
        if (p2 < CAP) g_bucket[(size_t)d.z * CAP + p2] = s.z;
        else { int o = atomicAdd(&g_ovf_cnt, 1); if (o < OVF_MAX) g_ovf[o] = make_int2(d.z, s.z); }
        if (p3 < CAP) g_bucket[(size_t)d.w * CAP + p3] = s.w;
        else { int o = atomicAdd(&g_ovf_cnt, 1); if (o < OVF_MAX) g_ovf[o] = make_int2(d.w, s.w); }
    } else {
        for (int i = base; i < n_edges; ++i) {
            int d = __ldg(edge_dst + i);
            int s = __ldg(edge_src + i);
            int p = atomicAdd(&g_cnt[d], 1);
            if (p < CAP) g_bucket[(size_t)d * CAP + p] = s;
            else { int o = atomicAdd(&g_ovf_cnt, 1); if (o < OVF_MAX) g_ovf[o] = make_int2(d, s); }
        }
    }
}

// ---------- main gather (16 threads per node, float4 per lane) ----------

__global__ void __launch_bounds__(256) gin_gather_kernel(
    const float4* __restrict__ feat,
    const float* __restrict__ eps,
    float4* __restrict__ out,
    int n_nodes) {
    int gid = blockIdx.x * blockDim.x + threadIdx.x;
    int node = gid >> 4;
    int lane = gid & 15;
    if (node >= n_nodes) return;

    int cnt = g_cnt[node];
    int deg = cnt < CAP ? cnt : CAP;
    const int* bkt = g_bucket + (size_t)node * CAP;

    float4 acc = make_float4(0.f, 0.f, 0.f, 0.f);

    int e = 0;
    for (; e + 4 <= deg; e += 4) {
        int s0 = bkt[e];
        int s1 = bkt[e + 1];
        int s2 = bkt[e + 2];
        int s3 = bkt[e + 3];
        float4 v0 = __ldg(feat + (size_t)s0 * D4 + lane);
        float4 v1 = __ldg(feat + (size_t)s1 * D4 + lane);
        float4 v2 = __ldg(feat + (size_t)s2 * D4 + lane);
        float4 v3 = __ldg(feat + (size_t)s3 * D4 + lane);
        acc.x += v0.x + v1.x + v2.x + v3.x;
        acc.y += v0.y + v1.y + v2.y + v3.y;
        acc.z += v0.z + v1.z + v2.z + v3.z;
        acc.w += v0.w + v1.w + v2.w + v3.w;
    }
    for (; e < deg; ++e) {
        int s = bkt[e];
        float4 v = __ldg(feat + (size_t)s * D4 + lane);
        acc.x += v.x; acc.y += v.y; acc.z += v.z; acc.w += v.w;
    }

    float sc = 1.0f + __ldg(eps);
    float4 f = __ldg(feat + (size_t)node * D4 + lane);
    float4 o;
    o.x = fmaf(sc, f.x, acc.x);
    o.y = fmaf(sc, f.y, acc.y);
    o.z = fmaf(sc, f.z, acc.z);
    o.w = fmaf(sc, f.w, acc.w);
    out[(size_t)node * D4 + lane] = o;

    // maintain zero-invariant for next call
    if (lane == 0) g_cnt[node] = 0;
}

// ---------- overflow tail (expected count: 0; correctness insurance) ----------

__global__ void overflow_tail_kernel(const float4* __restrict__ feat,
                                     float4* __restrict__ out) {
    int n = g_ovf_cnt;
    if (n > OVF_MAX) n = OVF_MAX;
    for (int i = threadIdx.x; i < n; i += blockDim.x) {
        int2 e = g_ovf[i];
        const float4* src = feat + (size_t)e.y * D4;
        float4* dst = out + (size_t)e.x * D4;
#pragma unroll
        for (int l = 0; l < D4; ++l) {
            float4 v = __ldg(src + l);
            asm volatile(
                "red.global.add.v4.f32 [%0], {%1, %2, %3, %4};"
                :: "l"(dst + l), "f"(v.x), "f"(v.y), "f"(v.z), "f"(v.w)
                : "memory");
        }
    }
    __syncthreads();
    if (threadIdx.x == 0) g_ovf_cnt = 0;   // restore invariant
}

// ---------- fallback (atomic) path for unexpected shapes ----------

__global__ void gin_init_kernel(const float4* __restrict__ feat,
                                const float* __restrict__ eps,
                                float4* __restrict__ out,
                                int n4) {
    int i = blockIdx.x * blockDim.x + threadIdx.x;
    if (i >= n4) return;
    float s = 1.0f + __ldg(eps);
    float4 f = __ldg(feat + i);
    f.x *= s; f.y *= s; f.z *= s; f.w *= s;
    out[i] = f;
}

__global__ void __launch_bounds__(256) gin_edge_atomic_kernel(
    const float4* __restrict__ feat,
    const int* __restrict__ edge_src,
    const int* __restrict__ edge_dst,
    float4* __restrict__ out,
    int n_edges) {
    int gid = blockIdx.x * blockDim.x + threadIdx.x;
    int eid = gid >> 4;
    int lane = gid & 15;
    if (eid >= n_edges) return;
    int s = __ldg(edge_src + eid);
    int d = __ldg(edge_dst + eid);
    float4 v = __ldg(feat + (size_t)s * D4 + lane);
    float4* dst = out + (size_t)d * D4 + lane;
    asm volatile(
        "red.global.add.v4.f32 [%0], {%1, %2, %3, %4};"
        :: "l"(dst), "f"(v.x), "f"(v.y), "f"(v.z), "f"(v.w)
        : "memory");
}

extern "C" void kernel_launch(void* const* d_in, const int* in_sizes, int n_in,
                              void* d_out, int out_size) {
    const float* feat     = (const float*)d_in[0];
    const float* eps      = (const float*)d_in[1];
    const int*   edge_src = (const int*)d_in[2];
    const int*   edge_dst = (const int*)d_in[3];
    float*       out      = (float*)d_out;

    int n_feat  = in_sizes[0];          // N * 64
    int n_edges = in_sizes[2];          // E
    int n_nodes = n_feat / 64;

    if (n_nodes > N_MAX || n_edges > E_MAX) {
        int n4 = n_feat / 4;
        gin_init_kernel<<<(n4 + 255) / 256, 256>>>(
            (const float4*)feat, eps, (float4*)out, n4);
        long long total = (long long)n_edges * 16;
        gin_edge_atomic_kernel<<<(int)((total + 255) / 256), 256>>>(
            (const float4*)feat, edge_src, edge_dst, (float4*)out, n_edges);
        return;
    }

    int e4 = (n_edges + 3) / 4;

    // 1. scatter edges into fixed-capacity dst buckets (g_cnt zero by invariant)
    scatter_bucket_kernel<<<(e4 + 255) / 256, 256>>>(edge_src, edge_dst, n_edges);

    // 2. gather + residual; re-zeroes g_cnt
    {
        long long total = (long long)n_nodes * 16;
        gin_gather_kernel<<<(int)((total + 255) / 256), 256>>>(
            (const float4*)feat, eps, (float4*)out, n_nodes);
    }

    // 3. apply any overflow edges (expected none); re-zeroes g_ovf_cnt
    overflow_tail_kernel<<<1, 256>>>((const float4*)feat, (float4*)out);
}